// round 16
// baseline (speedup 1.0000x reference)
#include <cuda_runtime.h>
#include <cuda_fp16.h>
#include <math.h>

#define NN 100000
#define EE 3200000
#define DD 64
constexpr float EPSF = 0.01f;
#define SB ((NN + 255) / 256)   // 391 scan blocks
typedef unsigned long long u64;

// ---------------- packed f32x2 helpers (register-dup FFMA2 path) ----------------
__device__ __forceinline__ u64 pk2(float lo, float hi) {
    u64 r; asm("mov.b64 %0, {%1, %2};" : "=l"(r) : "f"(lo), "f"(hi)); return r;
}
__device__ __forceinline__ void upk2(u64 v, float& lo, float& hi) {
    asm("mov.b64 {%0, %1}, %2;" : "=f"(lo), "=f"(hi) : "l"(v));
}
__device__ __forceinline__ u64 ffma2(u64 a, u64 b, u64 c) {
    u64 d; asm("fma.rn.f32x2 %0, %1, %2, %3;" : "=l"(d) : "l"(a), "l"(b), "l"(c)); return d;
}

// ---------------- scratch (device globals; no allocation allowed) ----------------
__device__ __align__(16) float  g_x [NN * DD];   // node state h
__device__ __align__(16) float  g_v [NN * DD];   // velocity (vp after k1)
__device__ __align__(16) __half g_lxh[NN * DD];  // fp16 lx for the gather
__device__ __align__(16) float  g_a  [NN];
__device__ __align__(16) float  g_b  [NN];       // x@wb + rb
__device__ __align__(16) float2 g_ad [NN];       // (a, dinv)
// CSR by col (for agg) and by row (for deg)
__device__ __align__(16) int g_ccnt [NN];
__device__ __align__(16) int g_cptr [NN + 1];
__device__ __align__(16) int g_cfill[NN];
__device__ __align__(16) int g_src  [EE];        // source node per col-CSR slot
__device__ __align__(16) float2 g_ws [EE];       // (w, src-as-float) per col-CSR slot
__device__ __align__(16) int g_rcnt [NN];
__device__ __align__(16) int g_rptr [NN + 1];
__device__ __align__(16) int g_rfill[NN];
__device__ __align__(16) int g_rcol [EE];        // dest node per row-CSR slot
__device__ __align__(16) int g_rmap [EE];        // row-CSR slot -> col-CSR slot
__device__ __align__(16) int g_cpart[512];
__device__ __align__(16) int g_rpart[512];

// ---------------- CSR build (self-edges dropped: valid = row!=col) ----------------
__global__ void zero_cnt_kernel() {
    int i = blockIdx.x * blockDim.x + threadIdx.x;
    if (i < NN) { g_ccnt[i] = 0; g_rcnt[i] = 0; }
}

__global__ void count_kernel(const int* __restrict__ ei) {
    int e = blockIdx.x * blockDim.x + threadIdx.x;
    if (e >= EE) return;
    int r = ei[e], c = ei[EE + e];
    if (r == c) return;
    atomicAdd(&g_ccnt[c], 1);
    atomicAdd(&g_rcnt[r], 1);
}

// --- multi-block scan: partial sums -> scan partials -> expand ---
__global__ void partial_kernel() {
    __shared__ int smc[256], smr[256];
    int t = threadIdx.x;
    int i = blockIdx.x * 256 + t;
    int vc = (i < NN) ? g_ccnt[i] : 0;
    int vr = (i < NN) ? g_rcnt[i] : 0;
    smc[t] = vc; smr[t] = vr;
    __syncthreads();
#pragma unroll
    for (int off = 128; off; off >>= 1) {
        if (t < off) { smc[t] += smc[t + off]; smr[t] += smr[t + off]; }
        __syncthreads();
    }
    if (t == 0) { g_cpart[blockIdx.x] = smc[0]; g_rpart[blockIdx.x] = smr[0]; }
}

__global__ void scanpart_kernel() {
    __shared__ int smc[512], smr[512];
    int t = threadIdx.x;
    int vc = (t < SB) ? g_cpart[t] : 0;
    int vr = (t < SB) ? g_rpart[t] : 0;
    smc[t] = vc; smr[t] = vr;
    __syncthreads();
#pragma unroll
    for (int off = 1; off < 512; off <<= 1) {
        int ac = (t >= off) ? smc[t - off] : 0;
        int ar = (t >= off) ? smr[t - off] : 0;
        __syncthreads();
        smc[t] += ac; smr[t] += ar;
        __syncthreads();
    }
    if (t < SB) { g_cpart[t] = smc[t] - vc; g_rpart[t] = smr[t] - vr; }
    if (t == 511) { g_cptr[NN] = smc[511]; g_rptr[NN] = smr[511]; }
}

__global__ void expand_kernel() {
    __shared__ int smc[256], smr[256];
    int b = blockIdx.x, t = threadIdx.x;
    int i = b * 256 + t;
    int vc = (i < NN) ? g_ccnt[i] : 0;
    int vr = (i < NN) ? g_rcnt[i] : 0;
    smc[t] = vc; smr[t] = vr;
    __syncthreads();
#pragma unroll
    for (int off = 1; off < 256; off <<= 1) {
        int ac = (t >= off) ? smc[t - off] : 0;
        int ar = (t >= off) ? smr[t - off] : 0;
        __syncthreads();
        smc[t] += ac; smr[t] += ar;
        __syncthreads();
    }
    if (i < NN) {
        int pc = g_cpart[b] + smc[t] - vc;
        int pr = g_rpart[b] + smr[t] - vr;
        g_cptr[i] = pc; g_cfill[i] = pc;
        g_rptr[i] = pr; g_rfill[i] = pr;
    }
}

__global__ void scatter_kernel(const int* __restrict__ ei) {
    int e = blockIdx.x * blockDim.x + threadIdx.x;
    if (e >= EE) return;
    int r = ei[e], c = ei[EE + e];
    if (r == c) return;
    int sc = atomicAdd(&g_cfill[c], 1);
    g_src[sc] = r;
    int sr = atomicAdd(&g_rfill[r], 1);
    g_rcol[sr] = c;
    g_rmap[sr] = sc;   // row-slot -> col-slot
}

// ---------------- shared helpers ----------------
__device__ __forceinline__ void load_xtile(const float* __restrict__ X, float* Xs,
                                           int node0, int nrows, int tid) {
    // Xs[k][m], pitch 68 floats, 64x64 tile transposed
    for (int i = tid; i < 1024; i += 256) {
        int m = i >> 4, q = i & 15;
        float4 v = make_float4(0.f, 0.f, 0.f, 0.f);
        int node = node0 + m;
        if (node < nrows) v = reinterpret_cast<const float4*>(X)[node * 16 + q];
        int k = q * 4;
        Xs[(k + 0) * 68 + m] = v.x;
        Xs[(k + 1) * 68 + m] = v.y;
        Xs[(k + 2) * 68 + m] = v.z;
        Xs[(k + 3) * 68 + m] = v.w;
    }
}

__device__ __forceinline__ float gelu_tanh(float x) {
    float x3 = x * x * x;
    float t = tanhf(0.7978845608028654f * (x + 0.044715f * x3));
    return 0.5f * x * (1.0f + t);
}

// ---------------- generic GEMM (reg-dup FFMA2): Y = X @ W + bias ----------------
template <int BN>
__global__ void gemm_kernel(const float* __restrict__ X, const float* __restrict__ W,
                            const float* __restrict__ bias, float* __restrict__ Y,
                            int nrows) {
    __shared__ float Ws[64 * BN];
    __shared__ float Xs[64 * 68];
    int tid = threadIdx.x;
    for (int i = tid; i < 64 * BN / 4; i += 256)
        reinterpret_cast<float4*>(Ws)[i] = reinterpret_cast<const float4*>(W)[i];
    int node0 = blockIdx.x * 64;
    load_xtile(X, Xs, node0, nrows, tid);
    __syncthreads();

    constexpr int NT = BN / 16;
    constexpr int NP = NT / 2;
    int tm = tid & 15, tn = tid >> 4;
    int m0 = tm * 4;
    u64 acc[4][NP];
#pragma unroll
    for (int i = 0; i < 4; ++i)
#pragma unroll
        for (int j = 0; j < NP; ++j) acc[i][j] = 0ull;

#pragma unroll 4
    for (int k = 0; k < 64; ++k) {
        float4 xv = *reinterpret_cast<const float4*>(Xs + k * 68 + m0);
        u64 xp[4] = {pk2(xv.x, xv.x), pk2(xv.y, xv.y), pk2(xv.z, xv.z), pk2(xv.w, xv.w)};
        const u64* wrow = reinterpret_cast<const u64*>(Ws + k * BN + tn * NT);
        u64 wp[NP];
#pragma unroll
        for (int j = 0; j < NP; ++j) wp[j] = wrow[j];
#pragma unroll
        for (int i = 0; i < 4; ++i)
#pragma unroll
            for (int j = 0; j < NP; ++j) acc[i][j] = ffma2(xp[i], wp[j], acc[i][j]);
    }
    float br[NT];
#pragma unroll
    for (int j = 0; j < NT; ++j) br[j] = bias[tn * NT + j];
#pragma unroll
    for (int i = 0; i < 4; ++i) {
        int m = node0 + m0 + i;
        if (m < nrows) {
            float r[NT];
#pragma unroll
            for (int j = 0; j < NP; ++j) upk2(acc[i][j], r[2 * j], r[2 * j + 1]);
#pragma unroll
            for (int j = 0; j < NT; ++j) Y[m * BN + tn * NT + j] = r[j] + br[j];
        }
    }
}

// ---------------- k1p (reg-dup FFMA2): lx/diss/forc GEMMs + partial v update ------
// vp = v*(1 - EPS*relu(diss)) - EPS*lx + EPS*forc ; lx stored fp16 for gather.
__global__ void k1p_kernel(const float* __restrict__ Wl, const float* __restrict__ bl,
                           const float* __restrict__ Wd, const float* __restrict__ bd,
                           const float* __restrict__ Wf, const float* __restrict__ bf) {
    extern __shared__ float sm[];
    float* Ws = sm;              // 64 x 192 (cols: 0-63 lin, 64-127 diss, 128-191 forc)
    float* Xs = sm + 64 * 192;   // 64 x 68
    int tid = threadIdx.x;
    for (int i = tid; i < 3072; i += 256) {
        int k = i / 48, q = i % 48;
        const float* src = (q < 16) ? Wl : (q < 32) ? Wd : Wf;
        int qq = q & 15;
        reinterpret_cast<float4*>(Ws + k * 192)[q] =
            reinterpret_cast<const float4*>(src + k * 64)[qq];
    }
    int node0 = blockIdx.x * 64;
    load_xtile(g_x, Xs, node0, NN, tid);
    __syncthreads();

    int tm = tid & 15, tn = tid >> 4;
    int m0 = tm * 4;
    u64 acc[4][3][2];
#pragma unroll
    for (int i = 0; i < 4; ++i)
#pragma unroll
        for (int s = 0; s < 3; ++s) { acc[i][s][0] = 0ull; acc[i][s][1] = 0ull; }

#pragma unroll 4
    for (int k = 0; k < 64; ++k) {
        float4 xv = *reinterpret_cast<const float4*>(Xs + k * 68 + m0);
        u64 xp[4] = {pk2(xv.x, xv.x), pk2(xv.y, xv.y), pk2(xv.z, xv.z), pk2(xv.w, xv.w)};
#pragma unroll
        for (int s = 0; s < 3; ++s) {
            const u64* wrow = reinterpret_cast<const u64*>(Ws + k * 192 + s * 64 + tn * 4);
            u64 w0 = wrow[0], w1 = wrow[1];
#pragma unroll
            for (int i = 0; i < 4; ++i) {
                acc[i][s][0] = ffma2(xp[i], w0, acc[i][s][0]);
                acc[i][s][1] = ffma2(xp[i], w1, acc[i][s][1]);
            }
        }
    }
    float4 b_l = *reinterpret_cast<const float4*>(bl + tn * 4);
    float4 b_d = *reinterpret_cast<const float4*>(bd + tn * 4);
    float4 b_f = *reinterpret_cast<const float4*>(bf + tn * 4);
    float blr[4] = {b_l.x, b_l.y, b_l.z, b_l.w};
    float bdr[4] = {b_d.x, b_d.y, b_d.z, b_d.w};
    float bfr[4] = {b_f.x, b_f.y, b_f.z, b_f.w};
#pragma unroll
    for (int i = 0; i < 4; ++i) {
        int m = node0 + m0 + i;
        if (m < NN) {
            int o = m * 64 + tn * 4;
            float4 v4 = *reinterpret_cast<const float4*>(g_v + o);
            float vr[4] = {v4.x, v4.y, v4.z, v4.w};
            float al[4], ad[4], af[4];
            upk2(acc[i][0][0], al[0], al[1]); upk2(acc[i][0][1], al[2], al[3]);
            upk2(acc[i][1][0], ad[0], ad[1]); upk2(acc[i][1][1], ad[2], ad[3]);
            upk2(acc[i][2][0], af[0], af[1]); upk2(acc[i][2][1], af[2], af[3]);
            float lx[4], vp[4];
#pragma unroll
            for (int j = 0; j < 4; ++j) {
                lx[j] = al[j] + blr[j];
                float ds = fmaxf(ad[j] + bdr[j], 0.f);
                float fc = af[j] + bfr[j];
                vp[j] = vr[j] - EPSF * (lx[j] + ds * vr[j] - fc);
            }
            *reinterpret_cast<float4*>(g_v + o) = make_float4(vp[0], vp[1], vp[2], vp[3]);
            __half2* lh = reinterpret_cast<__half2*>(g_lxh + o);
            lh[0] = __floats2half2_rn(lx[0], lx[1]);
            lh[1] = __floats2half2_rn(lx[2], lx[3]);
        }
    }
}

// ---------------- a,b dots (side stream; feeds deg) -------------------------------
__global__ void ab_kernel(const float* __restrict__ res_w_blk,
                          const float* __restrict__ res_b_blk) {
    int warp = (blockIdx.x * blockDim.x + threadIdx.x) >> 5;
    int lane = threadIdx.x & 31;
    if (warp >= NN) return;
    float2 xv = reinterpret_cast<const float2*>(g_x)[warp * 32 + lane];
    float wa0 = res_w_blk[2 * lane], wa1 = res_w_blk[2 * lane + 1];
    float wb0 = res_w_blk[64 + 2 * lane], wb1 = res_w_blk[64 + 2 * lane + 1];
    float sa = xv.x * wa0 + xv.y * wa1;
    float sb = xv.x * wb0 + xv.y * wb1;
#pragma unroll
    for (int off = 16; off; off >>= 1) {
        sa += __shfl_xor_sync(0xFFFFFFFFu, sa, off);
        sb += __shfl_xor_sync(0xFFFFFFFFu, sb, off);
    }
    if (lane == 0) {
        g_a[warp] = sa;
        g_b[warp] = sb + res_b_blk[0];  // fold rb into b
    }
}

// ---------------- fused MLP block (reg-dup FFMA2): h += gelu(h@W1+b1)@W2+b2 -------
__global__ void mlp_kernel(const float* __restrict__ W1, const float* __restrict__ b1,
                           const float* __restrict__ W2, const float* __restrict__ b2) {
    extern __shared__ float sm[];
    float* W1s = sm;                 // 4096
    float* W2s = sm + 4096;          // 4096
    float* Xs  = sm + 8192;          // 64*68
    float* Ts  = sm + 8192 + 4352;   // 64*68
    int tid = threadIdx.x;
    for (int i = tid; i < 1024; i += 256) {
        reinterpret_cast<float4*>(W1s)[i] = reinterpret_cast<const float4*>(W1)[i];
        reinterpret_cast<float4*>(W2s)[i] = reinterpret_cast<const float4*>(W2)[i];
    }
    int node0 = blockIdx.x * 64;
    load_xtile(g_x, Xs, node0, NN, tid);
    __syncthreads();

    int tm = tid & 15, tn = tid >> 4;
    int m0 = tm * 4;
    u64 acc[4][2] = {{0ull, 0ull}, {0ull, 0ull}, {0ull, 0ull}, {0ull, 0ull}};

#pragma unroll 4
    for (int k = 0; k < 64; ++k) {
        float4 xv = *reinterpret_cast<const float4*>(Xs + k * 68 + m0);
        u64 xp[4] = {pk2(xv.x, xv.x), pk2(xv.y, xv.y), pk2(xv.z, xv.z), pk2(xv.w, xv.w)};
        const u64* wrow = reinterpret_cast<const u64*>(W1s + k * 64 + tn * 4);
        u64 w0 = wrow[0], w1 = wrow[1];
#pragma unroll
        for (int i = 0; i < 4; ++i) {
            acc[i][0] = ffma2(xp[i], w0, acc[i][0]);
            acc[i][1] = ffma2(xp[i], w1, acc[i][1]);
        }
    }
    float4 bb1 = *reinterpret_cast<const float4*>(b1 + tn * 4);
    float br1[4] = {bb1.x, bb1.y, bb1.z, bb1.w};
#pragma unroll
    for (int i = 0; i < 4; ++i) {
        float t[4];
        upk2(acc[i][0], t[0], t[1]);
        upk2(acc[i][1], t[2], t[3]);
#pragma unroll
        for (int j = 0; j < 4; ++j)
            Ts[(tn * 4 + j) * 68 + m0 + i] = gelu_tanh(t[j] + br1[j]);
    }
    __syncthreads();

    u64 acc2[4][2] = {{0ull, 0ull}, {0ull, 0ull}, {0ull, 0ull}, {0ull, 0ull}};
#pragma unroll 4
    for (int k = 0; k < 64; ++k) {
        float4 tv = *reinterpret_cast<const float4*>(Ts + k * 68 + m0);
        u64 tp[4] = {pk2(tv.x, tv.x), pk2(tv.y, tv.y), pk2(tv.z, tv.z), pk2(tv.w, tv.w)};
        const u64* wrow = reinterpret_cast<const u64*>(W2s + k * 64 + tn * 4);
        u64 w0 = wrow[0], w1 = wrow[1];
#pragma unroll
        for (int i = 0; i < 4; ++i) {
            acc2[i][0] = ffma2(tp[i], w0, acc2[i][0]);
            acc2[i][1] = ffma2(tp[i], w1, acc2[i][1]);
        }
    }
    float4 bb2 = *reinterpret_cast<const float4*>(b2 + tn * 4);
    float br2[4] = {bb2.x, bb2.y, bb2.z, bb2.w};
#pragma unroll
    for (int i = 0; i < 4; ++i) {
        int m = node0 + m0 + i;
        if (m < NN) {
            float r[4];
            upk2(acc2[i][0], r[0], r[1]);
            upk2(acc2[i][1], r[2], r[3]);
#pragma unroll
            for (int j = 0; j < 4; ++j) {
                int n = tn * 4 + j;
                g_x[m * 64 + n] = Xs[n * 68 + m0 + i] + r[j] + br2[j];
            }
        }
    }
}

// ---------------- deg + fused per-edge weight write (side stream) ------------------
// Pass 1: deg sum (butterfly leaves full sum in all lanes -> dinv everywhere).
// Pass 2: recompute z per edge (rcol/b cache-hot), write (w, src) to col-CSR slot.
__global__ void deg_kernel() {
    int warp = (blockIdx.x * blockDim.x + threadIdx.x) >> 5;
    int lane = threadIdx.x & 31;
    if (warp >= NN) return;
    int r = warp;
    int lo = g_rptr[r], hi = g_rptr[r + 1];
    float a_r = __ldg(&g_a[r]);
    float s = 0.f;
#pragma unroll 4
    for (int p = lo + lane; p < hi; p += 32) {
        int c = __ldg(&g_rcol[p]);
        float z = a_r + __ldg(&g_b[c]);
        if (z > 0.f) s += z;
    }
#pragma unroll
    for (int off = 16; off; off >>= 1) s += __shfl_xor_sync(0xFFFFFFFFu, s, off);
    float dinv = (s > 0.f) ? rsqrtf(s) : 0.f;
    if (lane == 0)
        g_ad[r] = make_float2(a_r, dinv);
    float rf = __int_as_float(r);
#pragma unroll 4
    for (int p = lo + lane; p < hi; p += 32) {
        int c = __ldg(&g_rcol[p]);
        float z = a_r + __ldg(&g_b[c]);
        float w = (z > 0.f) ? z * dinv : 0.f;
        g_ws[__ldg(&g_rmap[p])] = make_float2(w, rf);
    }
}

// ---------------- aggregation + v/x update (warp per destination node) ----------------
// Per edge: one 8B broadcast LDG of (w,src), warp-uniform skip, 128B gather.
// No ballot/ffs/shfl. Unrolled x4 for gather MLP.
__global__ void agg_kernel() {
    int warp = (blockIdx.x * blockDim.x + threadIdx.x) >> 5;
    int lane = threadIdx.x & 31;
    if (warp >= NN) return;
    int c = warp;
    int p = g_cptr[c], end = g_cptr[c + 1];
    float dc = __ldg(&g_ad[c]).y;
    float acc0 = 0.f, acc1 = 0.f;
    const __half2* lxh2 = reinterpret_cast<const __half2*>(g_lxh);

    int j = p;
    for (; j + 4 <= end; j += 4) {
        float2 e0 = __ldg(g_ws + j);
        float2 e1 = __ldg(g_ws + j + 1);
        float2 e2 = __ldg(g_ws + j + 2);
        float2 e3 = __ldg(g_ws + j + 3);
        if (e0.x > 0.f) {
            float2 lf = __half22float2(__ldg(lxh2 + __float_as_int(e0.y) * 32 + lane));
            acc0 = fmaf(e0.x, lf.x, acc0); acc1 = fmaf(e0.x, lf.y, acc1);
        }
        if (e1.x > 0.f) {
            float2 lf = __half22float2(__ldg(lxh2 + __float_as_int(e1.y) * 32 + lane));
            acc0 = fmaf(e1.x, lf.x, acc0); acc1 = fmaf(e1.x, lf.y, acc1);
        }
        if (e2.x > 0.f) {
            float2 lf = __half22float2(__ldg(lxh2 + __float_as_int(e2.y) * 32 + lane));
            acc0 = fmaf(e2.x, lf.x, acc0); acc1 = fmaf(e2.x, lf.y, acc1);
        }
        if (e3.x > 0.f) {
            float2 lf = __half22float2(__ldg(lxh2 + __float_as_int(e3.y) * 32 + lane));
            acc0 = fmaf(e3.x, lf.x, acc0); acc1 = fmaf(e3.x, lf.y, acc1);
        }
    }
    for (; j < end; ++j) {
        float2 e0 = __ldg(g_ws + j);
        if (e0.x > 0.f) {
            float2 lf = __half22float2(__ldg(lxh2 + __float_as_int(e0.y) * 32 + lane));
            acc0 = fmaf(e0.x, lf.x, acc0); acc1 = fmaf(e0.x, lf.y, acc1);
        }
    }
    int idx = c * 32 + lane;
    float2 vv = reinterpret_cast<float2*>(g_v)[idx];   // vp from k1
    float2 xx = reinterpret_cast<float2*>(g_x)[idx];
    vv.x += EPSF * dc * acc0;
    vv.y += EPSF * dc * acc1;
    xx.x += EPSF * vv.x;
    xx.y += EPSF * vv.y;
    reinterpret_cast<float2*>(g_v)[idx] = vv;
    reinterpret_cast<float2*>(g_x)[idx] = xx;
}

// ---------------- stream/event context (created once, on the uncaptured call) -----
struct StreamCtx {
    cudaStream_t s1;
    cudaEvent_t ev[24];
    StreamCtx() {
        cudaStreamCreateWithFlags(&s1, cudaStreamNonBlocking);
        for (int i = 0; i < 24; ++i)
            cudaEventCreateWithFlags(&ev[i], cudaEventDisableTiming);
    }
};
static StreamCtx& ctx() { static StreamCtx c; return c; }

// ---------------- host launch ----------------
extern "C" void kernel_launch(void* const* d_in, const int* in_sizes, int n_in,
                              void* d_out, int out_size) {
    const float* x_in    = (const float*)d_in[0];
    const int*   ei      = (const int*)  d_in[1];
    const float* enc_w   = (const float*)d_in[2];
    const float* enc_b   = (const float*)d_in[3];
    const float* vel_w   = (const float*)d_in[4];
    const float* vel_b   = (const float*)d_in[5];
    const float* res_w   = (const float*)d_in[6];
    const float* res_b   = (const float*)d_in[7];
    const float* lin_w   = (const float*)d_in[8];
    const float* lin_b   = (const float*)d_in[9];
    const float* diss_w  = (const float*)d_in[10];
    const float* diss_b  = (const float*)d_in[11];
    const float* forc_w  = (const float*)d_in[12];
    const float* forc_b  = (const float*)d_in[13];
    const float* mlp_w1  = (const float*)d_in[14];
    const float* mlp_b1  = (const float*)d_in[15];
    const float* mlp_w2  = (const float*)d_in[16];
    const float* mlp_b2  = (const float*)d_in[17];
    const float* dec_w   = (const float*)d_in[18];
    const float* dec_b   = (const float*)d_in[19];
    float* out = (float*)d_out;

    float *px, *pv;
    cudaGetSymbolAddress((void**)&px, g_x);
    cudaGetSymbolAddress((void**)&pv, g_v);

    StreamCtx& C = ctx();

    const int K1_SMEM  = (192 * 64 + 64 * 68) * 4;
    const int MLP_SMEM = (4096 + 4096 + 2 * 64 * 68) * 4;
    cudaFuncSetAttribute(k1p_kernel, cudaFuncAttributeMaxDynamicSharedMemorySize, K1_SMEM);
    cudaFuncSetAttribute(mlp_kernel, cudaFuncAttributeMaxDynamicSharedMemorySize, MLP_SMEM);

    const int GB = (NN + 63) / 64;          // 64-node GEMM tiles
    const int NB = (NN + 255) / 256;        // node elementwise (== SB)
    const int WB = (NN + 7) / 8;            // 8 warps (nodes) per 256-thread block
    const int EB = (EE + 255) / 256;        // edge-parallel

    int ecur = 0;

    // Fork side stream; run one-time CSR build there, overlapping encoder/vel.
    cudaEventRecord(C.ev[ecur], 0);
    cudaStreamWaitEvent(C.s1, C.ev[ecur], 0);
    ++ecur;
    zero_cnt_kernel<<<NB, 256, 0, C.s1>>>();
    count_kernel<<<EB, 256, 0, C.s1>>>(ei);
    partial_kernel<<<SB, 256, 0, C.s1>>>();
    scanpart_kernel<<<1, 512, 0, C.s1>>>();
    expand_kernel<<<SB, 256, 0, C.s1>>>();
    scatter_kernel<<<EB, 256, 0, C.s1>>>(ei);

    // encoder (main stream; independent of CSR build)
    gemm_kernel<64><<<GB, 256>>>(x_in, enc_w, enc_b, px, NN);

    for (int blk = 0; blk < 2; ++blk) {
        gemm_kernel<64><<<GB, 256>>>(px, vel_w + blk * 4096, vel_b + blk * 64, pv, NN);
        for (int it = 0; it < 4; ++it) {
            // fork: side stream runs ab -> deg(+weights) concurrently with k1p
            cudaEventRecord(C.ev[ecur], 0);
            cudaStreamWaitEvent(C.s1, C.ev[ecur], 0);
            ++ecur;
            k1p_kernel<<<GB, 256, K1_SMEM>>>(lin_w  + blk * 4096, lin_b  + blk * 64,
                                             diss_w + blk * 4096, diss_b + blk * 64,
                                             forc_w + blk * 4096, forc_b + blk * 64);
            ab_kernel<<<WB, 256, 0, C.s1>>>(res_w + blk * 128, res_b + blk);
            deg_kernel<<<WB, 256, 0, C.s1>>>();
            // join: agg needs both k1p (main-stream order) and side chain (event)
            cudaEventRecord(C.ev[ecur], C.s1);
            cudaStreamWaitEvent(0, C.ev[ecur], 0);
            ++ecur;
            agg_kernel<<<WB, 256>>>();
        }
        mlp_kernel<<<GB, 256, MLP_SMEM>>>(mlp_w1 + blk * 4096, mlp_b1 + blk * 64,
                                          mlp_w2 + blk * 4096, mlp_b2 + blk * 64);
    }

    // decoder
    gemm_kernel<32><<<GB, 256>>>(px, dec_w, dec_b, out, NN);
}

// round 17
// speedup vs baseline: 1.2020x; 1.2020x over previous
#include <cuda_runtime.h>
#include <cuda_fp16.h>
#include <math.h>

#define NN 100000
#define EE 3200000
#define DD 64
constexpr float EPSF = 0.01f;
#define SB ((NN + 255) / 256)   // 391 scan blocks
typedef unsigned long long u64;

// ---------------- packed f32x2 helpers (register-dup FFMA2 path) ----------------
__device__ __forceinline__ u64 pk2(float lo, float hi) {
    u64 r; asm("mov.b64 %0, {%1, %2};" : "=l"(r) : "f"(lo), "f"(hi)); return r;
}
__device__ __forceinline__ void upk2(u64 v, float& lo, float& hi) {
    asm("mov.b64 {%0, %1}, %2;" : "=f"(lo), "=f"(hi) : "l"(v));
}
__device__ __forceinline__ u64 ffma2(u64 a, u64 b, u64 c) {
    u64 d; asm("fma.rn.f32x2 %0, %1, %2, %3;" : "=l"(d) : "l"(a), "l"(b), "l"(c)); return d;
}

// ---------------- scratch (device globals; no allocation allowed) ----------------
__device__ __align__(16) float  g_x [NN * DD];   // node state h
__device__ __align__(16) float  g_v [NN * DD];   // velocity (vp after k1)
__device__ __align__(16) __half g_lxh[NN * DD];  // fp16 lx for the gather
__device__ __align__(16) float  g_a  [NN];
__device__ __align__(16) float  g_b  [NN];       // x@wb + rb
__device__ __align__(16) float2 g_ad [NN];       // (a, dinv)
// CSR by col (for agg) and by row (for deg)
__device__ __align__(16) int g_ccnt [NN];
__device__ __align__(16) int g_cptr [NN + 1];
__device__ __align__(16) int g_cfill[NN];
__device__ __align__(16) int g_src  [EE];        // source node per col-CSR slot
__device__ __align__(16) int g_rcnt [NN];
__device__ __align__(16) int g_rptr [NN + 1];
__device__ __align__(16) int g_rfill[NN];
__device__ __align__(16) int g_rcol [EE];        // dest node per row-CSR slot
__device__ __align__(16) int g_cpart[512];
__device__ __align__(16) int g_rpart[512];

// ---------------- CSR build (self-edges dropped: valid = row!=col) ----------------
__global__ void zero_cnt_kernel() {
    int i = blockIdx.x * blockDim.x + threadIdx.x;
    if (i < NN) { g_ccnt[i] = 0; g_rcnt[i] = 0; }
}

__global__ void count_kernel(const int* __restrict__ ei) {
    int e = blockIdx.x * blockDim.x + threadIdx.x;
    if (e >= EE) return;
    int r = ei[e], c = ei[EE + e];
    if (r == c) return;
    atomicAdd(&g_ccnt[c], 1);
    atomicAdd(&g_rcnt[r], 1);
}

// --- multi-block scan: partial sums -> scan partials -> expand ---
__global__ void partial_kernel() {
    __shared__ int smc[256], smr[256];
    int t = threadIdx.x;
    int i = blockIdx.x * 256 + t;
    int vc = (i < NN) ? g_ccnt[i] : 0;
    int vr = (i < NN) ? g_rcnt[i] : 0;
    smc[t] = vc; smr[t] = vr;
    __syncthreads();
#pragma unroll
    for (int off = 128; off; off >>= 1) {
        if (t < off) { smc[t] += smc[t + off]; smr[t] += smr[t + off]; }
        __syncthreads();
    }
    if (t == 0) { g_cpart[blockIdx.x] = smc[0]; g_rpart[blockIdx.x] = smr[0]; }
}

__global__ void scanpart_kernel() {
    __shared__ int smc[512], smr[512];
    int t = threadIdx.x;
    int vc = (t < SB) ? g_cpart[t] : 0;
    int vr = (t < SB) ? g_rpart[t] : 0;
    smc[t] = vc; smr[t] = vr;
    __syncthreads();
#pragma unroll
    for (int off = 1; off < 512; off <<= 1) {
        int ac = (t >= off) ? smc[t - off] : 0;
        int ar = (t >= off) ? smr[t - off] : 0;
        __syncthreads();
        smc[t] += ac; smr[t] += ar;
        __syncthreads();
    }
    if (t < SB) { g_cpart[t] = smc[t] - vc; g_rpart[t] = smr[t] - vr; }
    if (t == 511) { g_cptr[NN] = smc[511]; g_rptr[NN] = smr[511]; }
}

__global__ void expand_kernel() {
    __shared__ int smc[256], smr[256];
    int b = blockIdx.x, t = threadIdx.x;
    int i = b * 256 + t;
    int vc = (i < NN) ? g_ccnt[i] : 0;
    int vr = (i < NN) ? g_rcnt[i] : 0;
    smc[t] = vc; smr[t] = vr;
    __syncthreads();
#pragma unroll
    for (int off = 1; off < 256; off <<= 1) {
        int ac = (t >= off) ? smc[t - off] : 0;
        int ar = (t >= off) ? smr[t - off] : 0;
        __syncthreads();
        smc[t] += ac; smr[t] += ar;
        __syncthreads();
    }
    if (i < NN) {
        int pc = g_cpart[b] + smc[t] - vc;
        int pr = g_rpart[b] + smr[t] - vr;
        g_cptr[i] = pc; g_cfill[i] = pc;
        g_rptr[i] = pr; g_rfill[i] = pr;
    }
}

__global__ void scatter_kernel(const int* __restrict__ ei) {
    int e = blockIdx.x * blockDim.x + threadIdx.x;
    if (e >= EE) return;
    int r = ei[e], c = ei[EE + e];
    if (r == c) return;
    int sc = atomicAdd(&g_cfill[c], 1);
    g_src[sc] = r;
    int sr = atomicAdd(&g_rfill[r], 1);
    g_rcol[sr] = c;
}

// ---------------- shared helpers ----------------
__device__ __forceinline__ void load_xtile(const float* __restrict__ X, float* Xs,
                                           int node0, int nrows, int tid) {
    // Xs[k][m], pitch 68 floats, 64x64 tile transposed
    for (int i = tid; i < 1024; i += 256) {
        int m = i >> 4, q = i & 15;
        float4 v = make_float4(0.f, 0.f, 0.f, 0.f);
        int node = node0 + m;
        if (node < nrows) v = reinterpret_cast<const float4*>(X)[node * 16 + q];
        int k = q * 4;
        Xs[(k + 0) * 68 + m] = v.x;
        Xs[(k + 1) * 68 + m] = v.y;
        Xs[(k + 2) * 68 + m] = v.z;
        Xs[(k + 3) * 68 + m] = v.w;
    }
}

__device__ __forceinline__ float gelu_tanh(float x) {
    float x3 = x * x * x;
    float t = tanhf(0.7978845608028654f * (x + 0.044715f * x3));
    return 0.5f * x * (1.0f + t);
}

// ---------------- generic GEMM (reg-dup FFMA2): Y = X @ W + bias ----------------
template <int BN>
__global__ void gemm_kernel(const float* __restrict__ X, const float* __restrict__ W,
                            const float* __restrict__ bias, float* __restrict__ Y,
                            int nrows) {
    __shared__ float Ws[64 * BN];
    __shared__ float Xs[64 * 68];
    int tid = threadIdx.x;
    for (int i = tid; i < 64 * BN / 4; i += 256)
        reinterpret_cast<float4*>(Ws)[i] = reinterpret_cast<const float4*>(W)[i];
    int node0 = blockIdx.x * 64;
    load_xtile(X, Xs, node0, nrows, tid);
    __syncthreads();

    constexpr int NT = BN / 16;
    constexpr int NP = NT / 2;
    int tm = tid & 15, tn = tid >> 4;
    int m0 = tm * 4;
    u64 acc[4][NP];
#pragma unroll
    for (int i = 0; i < 4; ++i)
#pragma unroll
        for (int j = 0; j < NP; ++j) acc[i][j] = 0ull;

#pragma unroll 4
    for (int k = 0; k < 64; ++k) {
        float4 xv = *reinterpret_cast<const float4*>(Xs + k * 68 + m0);
        u64 xp[4] = {pk2(xv.x, xv.x), pk2(xv.y, xv.y), pk2(xv.z, xv.z), pk2(xv.w, xv.w)};
        const u64* wrow = reinterpret_cast<const u64*>(Ws + k * BN + tn * NT);
        u64 wp[NP];
#pragma unroll
        for (int j = 0; j < NP; ++j) wp[j] = wrow[j];
#pragma unroll
        for (int i = 0; i < 4; ++i)
#pragma unroll
            for (int j = 0; j < NP; ++j) acc[i][j] = ffma2(xp[i], wp[j], acc[i][j]);
    }
    float br[NT];
#pragma unroll
    for (int j = 0; j < NT; ++j) br[j] = bias[tn * NT + j];
#pragma unroll
    for (int i = 0; i < 4; ++i) {
        int m = node0 + m0 + i;
        if (m < nrows) {
            float r[NT];
#pragma unroll
            for (int j = 0; j < NP; ++j) upk2(acc[i][j], r[2 * j], r[2 * j + 1]);
#pragma unroll
            for (int j = 0; j < NT; ++j) Y[m * BN + tn * NT + j] = r[j] + br[j];
        }
    }
}

// ---------------- k1p (reg-dup FFMA2): lx/diss/forc GEMMs + partial v update ------
// vp = v*(1 - EPS*relu(diss)) - EPS*lx + EPS*forc ; lx stored fp16 for gather.
__global__ void k1p_kernel(const float* __restrict__ Wl, const float* __restrict__ bl,
                           const float* __restrict__ Wd, const float* __restrict__ bd,
                           const float* __restrict__ Wf, const float* __restrict__ bf) {
    extern __shared__ float sm[];
    float* Ws = sm;              // 64 x 192 (cols: 0-63 lin, 64-127 diss, 128-191 forc)
    float* Xs = sm + 64 * 192;   // 64 x 68
    int tid = threadIdx.x;
    for (int i = tid; i < 3072; i += 256) {
        int k = i / 48, q = i % 48;
        const float* src = (q < 16) ? Wl : (q < 32) ? Wd : Wf;
        int qq = q & 15;
        reinterpret_cast<float4*>(Ws + k * 192)[q] =
            reinterpret_cast<const float4*>(src + k * 64)[qq];
    }
    int node0 = blockIdx.x * 64;
    load_xtile(g_x, Xs, node0, NN, tid);
    __syncthreads();

    int tm = tid & 15, tn = tid >> 4;
    int m0 = tm * 4;
    u64 acc[4][3][2];
#pragma unroll
    for (int i = 0; i < 4; ++i)
#pragma unroll
        for (int s = 0; s < 3; ++s) { acc[i][s][0] = 0ull; acc[i][s][1] = 0ull; }

#pragma unroll 4
    for (int k = 0; k < 64; ++k) {
        float4 xv = *reinterpret_cast<const float4*>(Xs + k * 68 + m0);
        u64 xp[4] = {pk2(xv.x, xv.x), pk2(xv.y, xv.y), pk2(xv.z, xv.z), pk2(xv.w, xv.w)};
#pragma unroll
        for (int s = 0; s < 3; ++s) {
            const u64* wrow = reinterpret_cast<const u64*>(Ws + k * 192 + s * 64 + tn * 4);
            u64 w0 = wrow[0], w1 = wrow[1];
#pragma unroll
            for (int i = 0; i < 4; ++i) {
                acc[i][s][0] = ffma2(xp[i], w0, acc[i][s][0]);
                acc[i][s][1] = ffma2(xp[i], w1, acc[i][s][1]);
            }
        }
    }
    float4 b_l = *reinterpret_cast<const float4*>(bl + tn * 4);
    float4 b_d = *reinterpret_cast<const float4*>(bd + tn * 4);
    float4 b_f = *reinterpret_cast<const float4*>(bf + tn * 4);
    float blr[4] = {b_l.x, b_l.y, b_l.z, b_l.w};
    float bdr[4] = {b_d.x, b_d.y, b_d.z, b_d.w};
    float bfr[4] = {b_f.x, b_f.y, b_f.z, b_f.w};
#pragma unroll
    for (int i = 0; i < 4; ++i) {
        int m = node0 + m0 + i;
        if (m < NN) {
            int o = m * 64 + tn * 4;
            float4 v4 = *reinterpret_cast<const float4*>(g_v + o);
            float vr[4] = {v4.x, v4.y, v4.z, v4.w};
            float al[4], ad[4], af[4];
            upk2(acc[i][0][0], al[0], al[1]); upk2(acc[i][0][1], al[2], al[3]);
            upk2(acc[i][1][0], ad[0], ad[1]); upk2(acc[i][1][1], ad[2], ad[3]);
            upk2(acc[i][2][0], af[0], af[1]); upk2(acc[i][2][1], af[2], af[3]);
            float lx[4], vp[4];
#pragma unroll
            for (int j = 0; j < 4; ++j) {
                lx[j] = al[j] + blr[j];
                float ds = fmaxf(ad[j] + bdr[j], 0.f);
                float fc = af[j] + bfr[j];
                vp[j] = vr[j] - EPSF * (lx[j] + ds * vr[j] - fc);
            }
            *reinterpret_cast<float4*>(g_v + o) = make_float4(vp[0], vp[1], vp[2], vp[3]);
            __half2* lh = reinterpret_cast<__half2*>(g_lxh + o);
            lh[0] = __floats2half2_rn(lx[0], lx[1]);
            lh[1] = __floats2half2_rn(lx[2], lx[3]);
        }
    }
}

// ---------------- a,b dots (side stream; feeds deg) -------------------------------
__global__ void ab_kernel(const float* __restrict__ res_w_blk,
                          const float* __restrict__ res_b_blk) {
    int warp = (blockIdx.x * blockDim.x + threadIdx.x) >> 5;
    int lane = threadIdx.x & 31;
    if (warp >= NN) return;
    float2 xv = reinterpret_cast<const float2*>(g_x)[warp * 32 + lane];
    float wa0 = res_w_blk[2 * lane], wa1 = res_w_blk[2 * lane + 1];
    float wb0 = res_w_blk[64 + 2 * lane], wb1 = res_w_blk[64 + 2 * lane + 1];
    float sa = xv.x * wa0 + xv.y * wa1;
    float sb = xv.x * wb0 + xv.y * wb1;
#pragma unroll
    for (int off = 16; off; off >>= 1) {
        sa += __shfl_xor_sync(0xFFFFFFFFu, sa, off);
        sb += __shfl_xor_sync(0xFFFFFFFFu, sb, off);
    }
    if (lane == 0) {
        g_a[warp] = sa;
        g_b[warp] = sb + res_b_blk[0];  // fold rb into b
    }
}

// ---------------- fused MLP block (reg-dup FFMA2): h += gelu(h@W1+b1)@W2+b2 -------
__global__ void mlp_kernel(const float* __restrict__ W1, const float* __restrict__ b1,
                           const float* __restrict__ W2, const float* __restrict__ b2) {
    extern __shared__ float sm[];
    float* W1s = sm;                 // 4096
    float* W2s = sm + 4096;          // 4096
    float* Xs  = sm + 8192;          // 64*68
    float* Ts  = sm + 8192 + 4352;   // 64*68
    int tid = threadIdx.x;
    for (int i = tid; i < 1024; i += 256) {
        reinterpret_cast<float4*>(W1s)[i] = reinterpret_cast<const float4*>(W1)[i];
        reinterpret_cast<float4*>(W2s)[i] = reinterpret_cast<const float4*>(W2)[i];
    }
    int node0 = blockIdx.x * 64;
    load_xtile(g_x, Xs, node0, NN, tid);
    __syncthreads();

    int tm = tid & 15, tn = tid >> 4;
    int m0 = tm * 4;
    u64 acc[4][2] = {{0ull, 0ull}, {0ull, 0ull}, {0ull, 0ull}, {0ull, 0ull}};

#pragma unroll 4
    for (int k = 0; k < 64; ++k) {
        float4 xv = *reinterpret_cast<const float4*>(Xs + k * 68 + m0);
        u64 xp[4] = {pk2(xv.x, xv.x), pk2(xv.y, xv.y), pk2(xv.z, xv.z), pk2(xv.w, xv.w)};
        const u64* wrow = reinterpret_cast<const u64*>(W1s + k * 64 + tn * 4);
        u64 w0 = wrow[0], w1 = wrow[1];
#pragma unroll
        for (int i = 0; i < 4; ++i) {
            acc[i][0] = ffma2(xp[i], w0, acc[i][0]);
            acc[i][1] = ffma2(xp[i], w1, acc[i][1]);
        }
    }
    float4 bb1 = *reinterpret_cast<const float4*>(b1 + tn * 4);
    float br1[4] = {bb1.x, bb1.y, bb1.z, bb1.w};
#pragma unroll
    for (int i = 0; i < 4; ++i) {
        float t[4];
        upk2(acc[i][0], t[0], t[1]);
        upk2(acc[i][1], t[2], t[3]);
#pragma unroll
        for (int j = 0; j < 4; ++j)
            Ts[(tn * 4 + j) * 68 + m0 + i] = gelu_tanh(t[j] + br1[j]);
    }
    __syncthreads();

    u64 acc2[4][2] = {{0ull, 0ull}, {0ull, 0ull}, {0ull, 0ull}, {0ull, 0ull}};
#pragma unroll 4
    for (int k = 0; k < 64; ++k) {
        float4 tv = *reinterpret_cast<const float4*>(Ts + k * 68 + m0);
        u64 tp[4] = {pk2(tv.x, tv.x), pk2(tv.y, tv.y), pk2(tv.z, tv.z), pk2(tv.w, tv.w)};
        const u64* wrow = reinterpret_cast<const u64*>(W2s + k * 64 + tn * 4);
        u64 w0 = wrow[0], w1 = wrow[1];
#pragma unroll
        for (int i = 0; i < 4; ++i) {
            acc2[i][0] = ffma2(tp[i], w0, acc2[i][0]);
            acc2[i][1] = ffma2(tp[i], w1, acc2[i][1]);
        }
    }
    float4 bb2 = *reinterpret_cast<const float4*>(b2 + tn * 4);
    float br2[4] = {bb2.x, bb2.y, bb2.z, bb2.w};
#pragma unroll
    for (int i = 0; i < 4; ++i) {
        int m = node0 + m0 + i;
        if (m < NN) {
            float r[4];
            upk2(acc2[i][0], r[0], r[1]);
            upk2(acc2[i][1], r[2], r[3]);
#pragma unroll
            for (int j = 0; j < 4; ++j) {
                int n = tn * 4 + j;
                g_x[m * 64 + n] = Xs[n * 68 + m0 + i] + r[j] + br2[j];
            }
        }
    }
}

// ---------------- deg via row-CSR gather (no atomics) + dinv fused ----------------
__global__ void deg_kernel() {
    int warp = (blockIdx.x * blockDim.x + threadIdx.x) >> 5;
    int lane = threadIdx.x & 31;
    if (warp >= NN) return;
    int r = warp;
    int lo = g_rptr[r], hi = g_rptr[r + 1];
    float a_r = __ldg(&g_a[r]);
    float s = 0.f;
#pragma unroll 4
    for (int p = lo + lane; p < hi; p += 32) {
        int c = __ldg(&g_rcol[p]);
        float z = a_r + __ldg(&g_b[c]);
        if (z > 0.f) s += z;
    }
#pragma unroll
    for (int off = 16; off; off >>= 1) s += __shfl_xor_sync(0xFFFFFFFFu, s, off);
    if (lane == 0)
        g_ad[r] = make_float2(a_r, (s > 0.f) ? rsqrtf(s) : 0.f);
}

// ---------------- aggregation + v/x update (warp per destination node) ----------------
// R14 structure; (w,s) packed into ONE u32 per edge -> single shfl per slot.
// pack = (fp16_bits(w) << 17) | s   (w > 0 so sign bit is 0; s < 2^17)
__global__ void agg_kernel() {
    int warp = (blockIdx.x * blockDim.x + threadIdx.x) >> 5;
    int lane = threadIdx.x & 31;
    if (warp >= NN) return;
    int c = warp;
    int p = g_cptr[c], end = g_cptr[c + 1];
    float dc = __ldg(&g_ad[c]).y;
    float bc = __ldg(&g_b[c]);
    float acc0 = 0.f, acc1 = 0.f;
    const __half2* lxh2 = reinterpret_cast<const __half2*>(g_lxh);

    for (int base = p; base < end; base += 32) {
        int e = base + lane;
        unsigned pk = 0u;
        float w = 0.f;
        if (e < end) {
            int s = __ldg(&g_src[e]);
            float2 ads = __ldg(&g_ad[s]);
            float z = ads.x + bc;
            w = (z > 0.f) ? z * ads.y : 0.f;
            if (w > 0.f)
                pk = ((unsigned)__half_as_ushort(__float2half_rn(w)) << 17) | (unsigned)s;
        }
        unsigned mask = __ballot_sync(0xFFFFFFFFu, pk != 0u);
        while (mask) {
            int bb[8];
            bool vv_[8];
            bb[0] = __ffs(mask) - 1; mask &= mask - 1; vv_[0] = true;
#pragma unroll
            for (int q = 1; q < 8; ++q) {
                if (mask) { bb[q] = __ffs(mask) - 1; mask &= mask - 1; vv_[q] = true; }
                else      { bb[q] = bb[0]; vv_[q] = false; }
            }
            unsigned pq[8];
#pragma unroll
            for (int q = 0; q < 8; ++q)
                pq[q] = __shfl_sync(0xFFFFFFFFu, pk, bb[q]);
#pragma unroll
            for (int q = 1; q < 8; ++q) if (!vv_[q]) pq[q] = 0u;
            float wq[8]; int sq[8];
#pragma unroll
            for (int q = 0; q < 8; ++q) {
                wq[q] = __half2float(__ushort_as_half((unsigned short)(pq[q] >> 17)));
                sq[q] = (int)(pq[q] & 0x1FFFFu);
            }
            __half2 hq[8];
#pragma unroll
            for (int q = 0; q < 8; ++q) hq[q] = __ldg(lxh2 + sq[q] * 32 + lane);
#pragma unroll
            for (int q = 0; q < 8; ++q) {
                float2 lf = __half22float2(hq[q]);
                acc0 = fmaf(wq[q], lf.x, acc0);
                acc1 = fmaf(wq[q], lf.y, acc1);
            }
        }
    }
    int idx = c * 32 + lane;
    float2 vv = reinterpret_cast<float2*>(g_v)[idx];   // vp from k1
    float2 xx = reinterpret_cast<float2*>(g_x)[idx];
    vv.x += EPSF * dc * acc0;
    vv.y += EPSF * dc * acc1;
    xx.x += EPSF * vv.x;
    xx.y += EPSF * vv.y;
    reinterpret_cast<float2*>(g_v)[idx] = vv;
    reinterpret_cast<float2*>(g_x)[idx] = xx;
}

// ---------------- stream/event context (created once, on the uncaptured call) -----
struct StreamCtx {
    cudaStream_t s1;
    cudaEvent_t ev[24];
    StreamCtx() {
        cudaStreamCreateWithFlags(&s1, cudaStreamNonBlocking);
        for (int i = 0; i < 24; ++i)
            cudaEventCreateWithFlags(&ev[i], cudaEventDisableTiming);
    }
};
static StreamCtx& ctx() { static StreamCtx c; return c; }

// ---------------- host launch ----------------
extern "C" void kernel_launch(void* const* d_in, const int* in_sizes, int n_in,
                              void* d_out, int out_size) {
    const float* x_in    = (const float*)d_in[0];
    const int*   ei      = (const int*)  d_in[1];
    const float* enc_w   = (const float*)d_in[2];
    const float* enc_b   = (const float*)d_in[3];
    const float* vel_w   = (const float*)d_in[4];
    const float* vel_b   = (const float*)d_in[5];
    const float* res_w   = (const float*)d_in[6];
    const float* res_b   = (const float*)d_in[7];
    const float* lin_w   = (const float*)d_in[8];
    const float* lin_b   = (const float*)d_in[9];
    const float* diss_w  = (const float*)d_in[10];
    const float* diss_b  = (const float*)d_in[11];
    const float* forc_w  = (const float*)d_in[12];
    const float* forc_b  = (const float*)d_in[13];
    const float* mlp_w1  = (const float*)d_in[14];
    const float* mlp_b1  = (const float*)d_in[15];
    const float* mlp_w2  = (const float*)d_in[16];
    const float* mlp_b2  = (const float*)d_in[17];
    const float* dec_w   = (const float*)d_in[18];
    const float* dec_b   = (const float*)d_in[19];
    float* out = (float*)d_out;

    float *px, *pv;
    cudaGetSymbolAddress((void**)&px, g_x);
    cudaGetSymbolAddress((void**)&pv, g_v);

    StreamCtx& C = ctx();

    const int K1_SMEM  = (192 * 64 + 64 * 68) * 4;
    const int MLP_SMEM = (4096 + 4096 + 2 * 64 * 68) * 4;
    cudaFuncSetAttribute(k1p_kernel, cudaFuncAttributeMaxDynamicSharedMemorySize, K1_SMEM);
    cudaFuncSetAttribute(mlp_kernel, cudaFuncAttributeMaxDynamicSharedMemorySize, MLP_SMEM);

    const int GB = (NN + 63) / 64;          // 64-node GEMM tiles
    const int NB = (NN + 255) / 256;        // node elementwise (== SB)
    const int WB = (NN + 7) / 8;            // 8 warps (nodes) per 256-thread block
    const int EB = (EE + 255) / 256;        // edge-parallel

    int ecur = 0;

    // Fork side stream; run one-time CSR build there, overlapping encoder/vel.
    cudaEventRecord(C.ev[ecur], 0);
    cudaStreamWaitEvent(C.s1, C.ev[ecur], 0);
    ++ecur;
    zero_cnt_kernel<<<NB, 256, 0, C.s1>>>();
    count_kernel<<<EB, 256, 0, C.s1>>>(ei);
    partial_kernel<<<SB, 256, 0, C.s1>>>();
    scanpart_kernel<<<1, 512, 0, C.s1>>>();
    expand_kernel<<<SB, 256, 0, C.s1>>>();
    scatter_kernel<<<EB, 256, 0, C.s1>>>(ei);

    // encoder (main stream; independent of CSR build)
    gemm_kernel<64><<<GB, 256>>>(x_in, enc_w, enc_b, px, NN);

    for (int blk = 0; blk < 2; ++blk) {
        gemm_kernel<64><<<GB, 256>>>(px, vel_w + blk * 4096, vel_b + blk * 64, pv, NN);
        for (int it = 0; it < 4; ++it) {
            // fork: side stream runs ab -> deg concurrently with the big k1p GEMM
            cudaEventRecord(C.ev[ecur], 0);
            cudaStreamWaitEvent(C.s1, C.ev[ecur], 0);
            ++ecur;
            k1p_kernel<<<GB, 256, K1_SMEM>>>(lin_w  + blk * 4096, lin_b  + blk * 64,
                                             diss_w + blk * 4096, diss_b + blk * 64,
                                             forc_w + blk * 4096, forc_b + blk * 64);
            ab_kernel<<<WB, 256, 0, C.s1>>>(res_w + blk * 128, res_b + blk);
            deg_kernel<<<WB, 256, 0, C.s1>>>();
            // join: agg needs both k1p (main-stream order) and ab/deg (event)
            cudaEventRecord(C.ev[ecur], C.s1);
            cudaStreamWaitEvent(0, C.ev[ecur], 0);
            ++ecur;
            agg_kernel<<<WB, 256>>>();
        }
        mlp_kernel<<<GB, 256, MLP_SMEM>>>(mlp_w1 + blk * 4096, mlp_b1 + blk * 64,
                                          mlp_w2 + blk * 4096, mlp_b2 + blk * 64);
    }

    // decoder
    gemm_kernel<32><<<GB, 256>>>(px, dec_w, dec_b, out, NN);
}